// round 6
// baseline (speedup 1.0000x reference)
#include <cuda_runtime.h>
#include <cuda_bf16.h>
#include <cstdint>

#define BATCH 2
#define NBOX  20000
#define CH    256
#define KTOP  5000
#define KP    5120
#define NLAYERS 6
#define CANDMAX 8192

// ---------------- scratch (no allocations allowed) ----------------
__device__ unsigned long long g_cand[BATCH * CANDMAX];
__device__ int            g_thrb[BATCH];
__device__ int            g_cnt[BATCH];
__device__ int            g_keep[BATCH * KTOP];
__device__ float4         g_boxk[BATCH * KTOP];
__device__ float          g_areak[BATCH * KTOP];
__device__ unsigned int   g_flags[BATCH * KTOP];
__device__ __nv_bfloat16  g_xb0[BATCH * KP * CH];
__device__ __nv_bfloat16  g_xb1[BATCH * KP * CH];
__device__ __nv_bfloat16  g_Wbf[NLAYERS * CH * CH];

__device__ __forceinline__ uint32_t smem_u32(const void* p) {
    uint32_t a;
    asm("{ .reg .u64 t; cvta.to.shared.u64 t, %1; cvt.u32.u64 %0, t; }" : "=r"(a) : "l"(p));
    return a;
}

// ---------------- 0) convert W to bf16 ----------------
__global__ void k_prep(const float* __restrict__ W) {
    int i = blockIdx.x * blockDim.x + threadIdx.x;
    if (i < NLAYERS * CH * CH) g_Wbf[i] = __float2bfloat16_rn(W[i]);
}

// ---------------- 1) histogram -> threshold bucket; zero cand/cnt ----------------
__global__ void s1_hist(const float* __restrict__ score) {
    __shared__ uint32_t hist[8192];
    __shared__ uint32_t part[1024];
    int b = blockIdx.x, tid = threadIdx.x;
#pragma unroll
    for (int q = 0; q < 8; q++) hist[tid + q * 1024] = 0;
    for (int q = tid; q < CANDMAX; q += 1024) g_cand[b * CANDMAX + q] = 0ull;
    __syncthreads();
    for (int n = tid; n < NBOX; n += 1024) {
        unsigned bits = __float_as_uint(score[b * NBOX + n]);
        atomicAdd(&hist[bits >> 19], 1u);
    }
    __syncthreads();
    uint32_t cs = 0;
#pragma unroll
    for (int q = 7; q >= 0; q--) cs += hist[tid * 8 + q];
    part[tid] = cs;
    __syncthreads();
    for (int off = 1; off < 1024; off <<= 1) {
        uint32_t v = part[tid] + ((tid + off < 1024) ? part[tid + off] : 0u);
        __syncthreads();
        part[tid] = v;
        __syncthreads();
    }
    uint32_t s = (tid < 1023) ? part[tid + 1] : 0u;
#pragma unroll
    for (int q = 7; q >= 0; q--) {
        uint32_t ns = s + hist[tid * 8 + q];
        if (s < (uint32_t)KTOP && ns >= (uint32_t)KTOP) g_thrb[b] = tid * 8 + q;
        s = ns;
    }
    if (tid == 0) g_cnt[b] = 0;
}

// ---------------- 2) candidate compaction ----------------
__global__ void s2_collect(const float* __restrict__ score) {
    int i = blockIdx.x * blockDim.x + threadIdx.x;
    if (i >= BATCH * NBOX) return;
    int b = i / NBOX, n = i - b * NBOX;
    unsigned bits = __float_as_uint(score[b * NBOX + n]);
    if ((int)(bits >> 19) >= g_thrb[b]) {
        int pos = atomicAdd(&g_cnt[b], 1);
        if (pos < CANDMAX)
            g_cand[b * CANDMAX + pos] =
                ((unsigned long long)bits << 32) | (0xFFFFFFFFu - (unsigned)n);
    }
}

// ---------------- 3) single-CTA bitonic sort (desc) + scatter top-K ----------------
__global__ void __launch_bounds__(1024, 1)
k_sort(const float* __restrict__ box, float* __restrict__ out, int write_keep) {
    __shared__ unsigned long long sk[CANDMAX];
    int b = blockIdx.x, tid = threadIdx.x;
    for (int q = tid; q < CANDMAX; q += 1024) sk[q] = g_cand[b * CANDMAX + q];
    __syncthreads();
    for (int k = 2; k <= CANDMAX; k <<= 1) {
        for (int j = k >> 1; j > 0; j >>= 1) {
#pragma unroll 4
            for (int w = tid; w < CANDMAX / 2; w += 1024) {
                int pos = 2 * w - (w & (j - 1));
                bool desc = ((pos & k) == 0);
                unsigned long long a = sk[pos], c = sk[pos + j];
                if (desc ? (a < c) : (a > c)) { sk[pos] = c; sk[pos + j] = a; }
            }
            __syncthreads();
        }
    }
    // scatter: rank r = position in sorted array
    const float* bb = box + b * 4 * NBOX;
    for (int r = tid; r < KTOP; r += 1024) {
        unsigned long long key = sk[r];
        int idx = (int)(0xFFFFFFFFu - (unsigned)(key & 0xFFFFFFFFull));
        g_keep[b * KTOP + r] = idx;
        g_flags[b * KTOP + r] = 0u;
        float x1 = bb[idx], y1 = bb[NBOX + idx];
        float x2 = bb[2 * NBOX + idx], y2 = bb[3 * NBOX + idx];
        g_boxk[b * KTOP + r] = make_float4(x1, y1, x2, y2);
        g_areak[b * KTOP + r] = (x2 - x1) * (y2 - y1);
        if (write_keep) out[BATCH * KTOP + b * KTOP + r] = (float)idx;
    }
}

// ---------------- 4) IoU local-max flags (triangular grid, division-free) ----------------
__global__ void k_iou() {
    int p = blockIdx.x, b = blockIdx.y;
    int tj = (int)((sqrtf(8.f * p + 1.f) - 1.f) * 0.5f);
    while ((tj + 1) * (tj + 2) / 2 <= p) tj++;
    while (tj * (tj + 1) / 2 > p) tj--;
    int ti = p - tj * (tj + 1) / 2;          // ti <= tj
    __shared__ float4 sbx[128];
    __shared__ float  sar[128];
    int tid = threadIdx.x;
    int gi0 = ti * 128;
    int gl = gi0 + tid;
    if (gl < KTOP) { sbx[tid] = g_boxk[b * KTOP + gl]; sar[tid] = g_areak[b * KTOP + gl]; }
    __syncthreads();
    int j = tj * 128 + tid;
    if (j >= KTOP) return;
    float4 bj = g_boxk[b * KTOP + j];
    float  aj = g_areak[b * KTOP + j];
    int imax = min(KTOP, min(j, gi0 + 128)) - gi0;
    unsigned int fl = 0u;
    for (int i = 0; i < imax; i++) {
        float4 bi = sbx[i];
        float w = fminf(bi.z, bj.z) - fmaxf(bi.x, bj.x);
        float h = fminf(bi.w, bj.w) - fmaxf(bi.y, bj.y);
        w = fmaxf(w, 0.f); h = fmaxf(h, 0.f);
        float inter = w * h;
        float uni = sar[i] + aj - inter;
        if (inter >= 0.4f * uni) fl |= 1u;
        if (inter >= 0.6f * uni) fl |= 2u;
        if (inter >= 0.8f * uni) fl |= 4u;
        if (fl == 7u) break;
    }
    if (fl) atomicOr(&g_flags[b * KTOP + j], fl);
}

// ---------------- 5) bf16 mma.sync layer: M=160 tokens x N=128 outch x K=256 ----------------
#define TM     160
#define ROWB   528
#define TILEX  (TM * ROWB)            // 84480
#define TILEW  (128 * ROWB)           // 67584
#define SMEM_GEMM (TILEX + TILEW + 512)

__device__ __forceinline__ void ldm4(uint32_t* r, uint32_t addr) {
    asm volatile("ldmatrix.sync.aligned.m8n8.x4.shared.b16 {%0,%1,%2,%3}, [%4];"
                 : "=r"(r[0]), "=r"(r[1]), "=r"(r[2]), "=r"(r[3]) : "r"(addr));
}
__device__ __forceinline__ void mma16816(float* c, const uint32_t* a,
                                         uint32_t b0, uint32_t b1) {
    asm volatile(
        "mma.sync.aligned.m16n8k16.row.col.f32.bf16.bf16.f32 "
        "{%0,%1,%2,%3}, {%4,%5,%6,%7}, {%8,%9}, {%0,%1,%2,%3};"
        : "+f"(c[0]), "+f"(c[1]), "+f"(c[2]), "+f"(c[3])
        : "r"(a[0]), "r"(a[1]), "r"(a[2]), "r"(a[3]), "r"(b0), "r"(b1));
}

__global__ void __launch_bounds__(320, 1)
k_mma(const float* __restrict__ feat, const __nv_bfloat16* __restrict__ Xin,
      __nv_bfloat16* __restrict__ Yout, int layer, const float* __restrict__ bvec) {
    extern __shared__ char smem[];
    float* sbias = (float*)(smem + TILEX + TILEW);
    uint32_t sx = smem_u32(smem);
    uint32_t sw = sx + TILEX;
    int tid = threadIdx.x, wid = tid >> 5, lane = tid & 31;
    int bx = blockIdx.x, by = blockIdx.y, bz = blockIdx.z;

    // X tile: 160 tokens x 256 ch (5120 uint4 chunks)
    if (layer == 0) {
        const float* fb = feat + (size_t)bz * CH * NBOX;
        const int* kp = g_keep + bz * KTOP;
        for (int c = tid; c < TM * 32; c += 320) {
            int row = c >> 5, ch = (c & 31) * 8;
            int t = bx * TM + row;
            __nv_bfloat16 h[8];
            if (t < KTOP) {
                int idx = kp[t];
                const float* f = fb + idx;
#pragma unroll
                for (int q = 0; q < 8; q++)
                    h[q] = __float2bfloat16_rn(f[(size_t)(ch + q) * NBOX]);
            } else {
#pragma unroll
                for (int q = 0; q < 8; q++) h[q] = __float2bfloat16_rn(0.f);
            }
            *(uint4*)(smem + row * ROWB + ch * 2) = *(uint4*)h;
        }
    } else {
        const uint4* gX = (const uint4*)(Xin + ((size_t)bz * KP + (size_t)bx * TM) * CH);
        for (int c = tid; c < TM * 32; c += 320) {
            int row = c >> 5, ch = (c & 31) * 8;
            *(uint4*)(smem + row * ROWB + ch * 2) = gX[c];
        }
    }
    // W tile: 128 outch x 256 (4096 chunks)
    {
        const uint4* gW = (const uint4*)(g_Wbf + (size_t)layer * CH * CH + (size_t)by * 128 * CH);
        for (int c = tid; c < 4096; c += 320) {
            int row = c >> 5, ch = (c & 31) * 8;
            *(uint4*)(smem + TILEX + row * ROWB + ch * 2) = gW[c];
        }
    }
    if (tid < 128) sbias[tid] = bvec[layer * CH + by * 128 + tid];
    __syncthreads();

    int wm = wid % 5, wn = wid / 5;        // 5 x 2 warp grid; warp tile 32(M) x 64(N)
    float acc[2][8][4];
#pragma unroll
    for (int i = 0; i < 2; i++)
#pragma unroll
        for (int j = 0; j < 8; j++)
#pragma unroll
            for (int q = 0; q < 4; q++) acc[i][j][q] = 0.f;

    int a_row  = lane & 15;
    int a_koff = (lane >> 4) * 8;
    int b_row  = (lane & 7) + ((lane >> 4) << 3);
    int b_koff = ((lane >> 3) & 1) * 8;
    uint32_t xbase = sx + (uint32_t)(wm * 32) * ROWB;
    uint32_t wbase = sw + (uint32_t)(wn * 64) * ROWB;

#pragma unroll 4
    for (int kk = 0; kk < 256; kk += 16) {
        uint32_t a[2][4];
#pragma unroll
        for (int mi = 0; mi < 2; mi++)
            ldm4(a[mi], xbase + (uint32_t)(mi * 16 + a_row) * ROWB + (kk + a_koff) * 2);
        uint32_t bfr[4][4];
#pragma unroll
        for (int ni = 0; ni < 4; ni++)
            ldm4(bfr[ni], wbase + (uint32_t)(ni * 16 + b_row) * ROWB + (kk + b_koff) * 2);
#pragma unroll
        for (int mi = 0; mi < 2; mi++)
#pragma unroll
            for (int nj = 0; nj < 8; nj++)
                mma16816(acc[mi][nj], a[mi], bfr[nj >> 1][(nj & 1) * 2],
                         bfr[nj >> 1][(nj & 1) * 2 + 1]);
    }

    int tq = lane >> 2, tr = lane & 3;
    __nv_bfloat16* Yb = Yout + ((size_t)bz * KP + (size_t)bx * TM) * CH + (size_t)by * 128;
#pragma unroll
    for (int mi = 0; mi < 2; mi++) {
#pragma unroll
        for (int nj = 0; nj < 8; nj++) {
            int n = wn * 64 + nj * 8 + tr * 2;
            float b0v = sbias[n], b1v = sbias[n + 1];
            int m0 = wm * 32 + mi * 16 + tq;
#pragma unroll
            for (int h = 0; h < 2; h++) {
                float v0 = acc[mi][nj][h * 2 + 0] + b0v;
                float v1 = acc[mi][nj][h * 2 + 1] + b1v;
                v0 = v0 > 0.f ? v0 : 0.2f * v0;
                v1 = v1 > 0.f ? v1 : 0.2f * v1;
                __nv_bfloat162 pk;
                pk.x = __float2bfloat16_rn(v0);
                pk.y = __float2bfloat16_rn(v1);
                *(__nv_bfloat162*)(Yb + (size_t)(m0 + h * 8) * CH + n) = pk;
            }
        }
    }
}

// ---------------- 6) final head: warp per token ----------------
__global__ void k_final(const float* __restrict__ Wf, const float* __restrict__ bf,
                        float* __restrict__ out) {
    int w = (blockIdx.x * blockDim.x + threadIdx.x) >> 5;
    int lane = threadIdx.x & 31;
    if (w >= BATCH * KTOP) return;
    int b = w / KTOP, t = w - b * KTOP;
    const uint4* x = (const uint4*)(g_xb0 + ((size_t)b * KP + t) * CH);
    uint4 raw = x[lane];
    __nv_bfloat16 h[8];
    *(uint4*)h = raw;
    float l0 = 0.f, l1 = 0.f, l2 = 0.f;
    int c0 = lane * 8;
#pragma unroll
    for (int q = 0; q < 8; q++) {
        float xv = __bfloat162float(h[q]);
        l0 += Wf[c0 + q] * xv;
        l1 += Wf[CH + c0 + q] * xv;
        l2 += Wf[2 * CH + c0 + q] * xv;
    }
#pragma unroll
    for (int o = 16; o; o >>= 1) {
        l0 += __shfl_xor_sync(0xFFFFFFFFu, l0, o);
        l1 += __shfl_xor_sync(0xFFFFFFFFu, l1, o);
        l2 += __shfl_xor_sync(0xFFFFFFFFu, l2, o);
    }
    if (lane == 0) {
        l0 += bf[0]; l1 += bf[1]; l2 += bf[2];
        float m = fmaxf(l0, fmaxf(l1, l2));
        float e0 = expf(l0 - m), e1 = expf(l1 - m), e2 = expf(l2 - m);
        float inv = 1.f / (e0 + e1 + e2);
        unsigned int fl = g_flags[b * KTOP + t];
        float loc = 0.f;
        if (!(fl & 1u)) loc += e0 * inv;
        if (!(fl & 2u)) loc += e1 * inv;
        if (!(fl & 4u)) loc += e2 * inv;
        out[b * KTOP + t] = loc;
    }
}

// ---------------- launch ----------------
extern "C" void kernel_launch(void* const* d_in, const int* in_sizes, int n_in,
                              void* d_out, int out_size) {
    const float* box   = (const float*)d_in[0];
    const float* score = (const float*)d_in[1];
    const float* feat  = (const float*)d_in[2];
    const float* W     = (const float*)d_in[3];
    const float* bvec  = (const float*)d_in[4];
    const float* Wf    = (const float*)d_in[5];
    const float* bf    = (const float*)d_in[6];
    float* out = (float*)d_out;
    int write_keep = (out_size >= 2 * BATCH * KTOP) ? 1 : 0;

    static int init_done = 0;
    static __nv_bfloat16 *x0p = nullptr, *x1p = nullptr;
    if (!init_done) {
        cudaFuncSetAttribute(k_mma, cudaFuncAttributeMaxDynamicSharedMemorySize, SMEM_GEMM);
        cudaGetSymbolAddress((void**)&x0p, g_xb0);
        cudaGetSymbolAddress((void**)&x1p, g_xb1);
        init_done = 1;
    }

    k_prep<<<(NLAYERS * CH * CH + 255) / 256, 256>>>(W);
    s1_hist<<<BATCH, 1024>>>(score);
    s2_collect<<<(BATCH * NBOX + 255) / 256, 256>>>(score);
    k_sort<<<BATCH, 1024>>>(box, out, write_keep);
    k_iou<<<dim3(820, BATCH), 128>>>();
    // L0 gathers from feat -> xb1; then ping-pong; L5 writes xb0 (read by k_final)
    k_mma<<<dim3(KP / TM, 2, BATCH), 320, SMEM_GEMM>>>(feat, nullptr, x1p, 0, bvec);
    for (int l = 1; l < NLAYERS; l++) {
        const __nv_bfloat16* Xi = (l & 1) ? x1p : x0p;
        __nv_bfloat16*       Yo = (l & 1) ? x0p : x1p;
        k_mma<<<dim3(KP / TM, 2, BATCH), 320, SMEM_GEMM>>>(feat, Xi, Yo, l, bvec);
    }
    k_final<<<(BATCH * KTOP + 7) / 8, 256>>>(Wf, bf, out);
}

// round 7
// speedup vs baseline: 1.4434x; 1.4434x over previous
#include <cuda_runtime.h>
#include <cuda_bf16.h>
#include <cstdint>

#define BATCH 2
#define NBOX  20000
#define CH    256
#define KTOP  5000
#define KP    5120
#define NLAYERS 6
#define CANDMAX 8192
#define NBUCKET 8192

// ---------------- scratch (no allocations allowed) ----------------
__device__ unsigned long long g_cand[BATCH * CANDMAX];
__device__ int            g_thrb[BATCH];
__device__ int            g_bstart[BATCH * NBUCKET];
__device__ int            g_boff[BATCH * NBUCKET];
__device__ int            g_keep[BATCH * KTOP];
__device__ float4         g_boxk[BATCH * KTOP];
__device__ float          g_areak[BATCH * KTOP];
__device__ unsigned int   g_flags[BATCH * KTOP];
__device__ __nv_bfloat16  g_xb0[BATCH * KP * CH];
__device__ __nv_bfloat16  g_xb1[BATCH * KP * CH];
__device__ __nv_bfloat16  g_Wbf[NLAYERS * CH * CH];

__device__ __forceinline__ uint32_t smem_u32(const void* p) {
    uint32_t a;
    asm("{ .reg .u64 t; cvta.to.shared.u64 t, %1; cvt.u32.u64 %0, t; }" : "=r"(a) : "l"(p));
    return a;
}

// ---------------- 0) convert W to bf16 ----------------
__global__ void k_prep(const float* __restrict__ W) {
    int i = blockIdx.x * blockDim.x + threadIdx.x;
    if (i < NLAYERS * CH * CH) g_Wbf[i] = __float2bfloat16_rn(W[i]);
}

// ---------------- 1) histogram -> per-bucket descending start offsets + threshold ----------------
// scores positive floats -> bucket = bits>>19 monotone in score (higher bucket = higher score).
__global__ void s1_hist(const float* __restrict__ score) {
    __shared__ uint32_t hist[NBUCKET];
    __shared__ uint32_t part[1024];
    int b = blockIdx.x, tid = threadIdx.x;
#pragma unroll
    for (int q = 0; q < 8; q++) hist[tid + q * 1024] = 0;
    __syncthreads();
    for (int n = tid; n < NBOX; n += 1024) {
        unsigned bits = __float_as_uint(score[b * NBOX + n]);
        atomicAdd(&hist[bits >> 19], 1u);
    }
    __syncthreads();
    uint32_t cs = 0;
#pragma unroll
    for (int q = 7; q >= 0; q--) cs += hist[tid * 8 + q];
    part[tid] = cs;
    __syncthreads();
    for (int off = 1; off < 1024; off <<= 1) {
        uint32_t v = part[tid] + ((tid + off < 1024) ? part[tid + off] : 0u);
        __syncthreads();
        part[tid] = v;
        __syncthreads();
    }
    uint32_t s = (tid < 1023) ? part[tid + 1] : 0u;   // elems in buckets above this chunk
#pragma unroll
    for (int q = 7; q >= 0; q--) {
        int v = tid * 8 + q;
        g_bstart[b * NBUCKET + v] = (int)s;
        g_boff[b * NBUCKET + v]   = (int)s;
        uint32_t ns = s + hist[v];
        if (s < (uint32_t)KTOP && ns >= (uint32_t)KTOP) g_thrb[b] = v;
        s = ns;
    }
}

// ---------------- 2) counting-sort scatter into bucket regions ----------------
__global__ void s2_scatter(const float* __restrict__ score) {
    int i = blockIdx.x * blockDim.x + threadIdx.x;
    if (i >= BATCH * NBOX) return;
    int b = i / NBOX, n = i - b * NBOX;
    unsigned bits = __float_as_uint(score[b * NBOX + n]);
    int v = (int)(bits >> 19);
    if (v >= g_thrb[b]) {
        int pos = atomicAdd(&g_boff[b * NBUCKET + v], 1);
        if (pos < CANDMAX)
            g_cand[b * CANDMAX + pos] =
                ((unsigned long long)bits << 32) | (0xFFFFFFFFu - (unsigned)n);
    }
}

// ---------------- 3) exact rank within bucket + scatter top-K ----------------
__global__ void s3_rank(const float* __restrict__ box, float* __restrict__ out,
                        int write_keep) {
    int b = blockIdx.y;
    int p = blockIdx.x * 256 + threadIdx.x;
    int thrb = g_thrb[b];
    int tot = min(g_boff[b * NBUCKET + thrb], CANDMAX);
    if (p >= tot) return;
    unsigned long long key = g_cand[b * CANDMAX + p];
    int v = (int)(key >> 51);                         // bucket
    int s = g_bstart[b * NBUCKET + v];
    int e = min(g_boff[b * NBUCKET + v], CANDMAX);
    int r = s;
    for (int q = s; q < e; q++) r += (g_cand[b * CANDMAX + q] > key) ? 1 : 0;
    if (r >= KTOP) return;
    int idx = (int)(0xFFFFFFFFu - (unsigned)(key & 0xFFFFFFFFull));
    g_keep[b * KTOP + r] = idx;
    g_flags[b * KTOP + r] = 0u;
    const float* bb = box + b * 4 * NBOX;
    float x1 = bb[idx], y1 = bb[NBOX + idx], x2 = bb[2 * NBOX + idx], y2 = bb[3 * NBOX + idx];
    g_boxk[b * KTOP + r] = make_float4(x1, y1, x2, y2);
    g_areak[b * KTOP + r] = (x2 - x1) * (y2 - y1);
    if (write_keep) out[BATCH * KTOP + b * KTOP + r] = (float)idx;
}

// ---------------- gather: token-major bf16, one warp per token ----------------
__global__ void k_gather(const float* __restrict__ feat) {
    int w = (blockIdx.x * blockDim.x + threadIdx.x) >> 5;
    int lane = threadIdx.x & 31;
    if (w >= BATCH * KP) return;
    int b = w / KP, t = w - b * KP;
    uint4* dst = (uint4*)(g_xb0 + (size_t)w * CH);
    if (t >= KTOP) { dst[lane] = make_uint4(0, 0, 0, 0); return; }
    int idx = g_keep[b * KTOP + t];
    const float* f = feat + (size_t)b * CH * NBOX + idx;
    __nv_bfloat16 h[8];
#pragma unroll
    for (int q = 0; q < 8; q++)
        h[q] = __float2bfloat16_rn(f[(size_t)(lane * 8 + q) * NBOX]);
    dst[lane] = *(uint4*)h;
}

// ---------------- IoU local-max flags (division-free) ----------------
__global__ void k_iou() {
    int ti = blockIdx.x, tj = blockIdx.y, b = blockIdx.z;
    if (ti > tj) return;
    __shared__ float4 sbx[128];
    __shared__ float  sar[128];
    int tid = threadIdx.x;
    int gi0 = ti * 128;
    int gl = gi0 + tid;
    if (gl < KTOP) { sbx[tid] = g_boxk[b * KTOP + gl]; sar[tid] = g_areak[b * KTOP + gl]; }
    __syncthreads();
    int j = tj * 128 + tid;
    if (j >= KTOP) return;
    float4 bj = g_boxk[b * KTOP + j];
    float  aj = g_areak[b * KTOP + j];
    int imax = min(KTOP, min(j, gi0 + 128)) - gi0;
    unsigned int fl = 0u;
    for (int i = 0; i < imax; i++) {
        float4 bi = sbx[i];
        float w = fminf(bi.z, bj.z) - fmaxf(bi.x, bj.x);
        float h = fminf(bi.w, bj.w) - fmaxf(bi.y, bj.y);
        w = fmaxf(w, 0.f); h = fmaxf(h, 0.f);
        float inter = w * h;
        float uni = sar[i] + aj - inter;
        if (inter >= 0.4f * uni) fl |= 1u;
        if (inter >= 0.6f * uni) fl |= 2u;
        if (inter >= 0.8f * uni) fl |= 4u;
        if (fl == 7u) break;
    }
    if (fl) atomicOr(&g_flags[b * KTOP + j], fl);
}

// ---------------- bf16 mma.sync layer: 128 tokens x 128 outch x K=256 ----------------
#define ROWB   528
#define TILEB  (128 * ROWB)
#define SMEM_GEMM (2 * TILEB + 512)

__device__ __forceinline__ void ldm4(uint32_t* r, uint32_t addr) {
    asm volatile("ldmatrix.sync.aligned.m8n8.x4.shared.b16 {%0,%1,%2,%3}, [%4];"
                 : "=r"(r[0]), "=r"(r[1]), "=r"(r[2]), "=r"(r[3]) : "r"(addr));
}
__device__ __forceinline__ void mma16816(float* c, const uint32_t* a,
                                         uint32_t b0, uint32_t b1) {
    asm volatile(
        "mma.sync.aligned.m16n8k16.row.col.f32.bf16.bf16.f32 "
        "{%0,%1,%2,%3}, {%4,%5,%6,%7}, {%8,%9}, {%0,%1,%2,%3};"
        : "+f"(c[0]), "+f"(c[1]), "+f"(c[2]), "+f"(c[3])
        : "r"(a[0]), "r"(a[1]), "r"(a[2]), "r"(a[3]), "r"(b0), "r"(b1));
}

__global__ void __launch_bounds__(256, 1)
k_mma(const __nv_bfloat16* __restrict__ Xin, __nv_bfloat16* __restrict__ Yout,
      int layer, const float* __restrict__ bvec) {
    extern __shared__ char smem[];
    float* sbias = (float*)(smem + 2 * TILEB);
    uint32_t sx = smem_u32(smem);
    uint32_t sw = sx + TILEB;
    int tid = threadIdx.x, wid = tid >> 5, lane = tid & 31;
    int bx = blockIdx.x, by = blockIdx.y, bz = blockIdx.z;

    const uint4* gX = (const uint4*)(Xin + ((size_t)bz * KP + (size_t)bx * 128) * CH);
    const uint4* gW = (const uint4*)(g_Wbf + (size_t)layer * CH * CH + (size_t)by * 128 * CH);
#pragma unroll
    for (int it = 0; it < 16; it++) {
        int c = tid + it * 256;
        int row = c >> 5, ch = (c & 31) * 8;
        *(uint4*)(smem + row * ROWB + ch * 2)         = gX[c];
        *(uint4*)(smem + TILEB + row * ROWB + ch * 2) = gW[c];
    }
    if (tid < 128) sbias[tid] = bvec[layer * CH + by * 128 + tid];
    __syncthreads();

    int wm = wid & 3, wn = wid >> 2;
    float acc[2][8][4];
#pragma unroll
    for (int i = 0; i < 2; i++)
#pragma unroll
        for (int j = 0; j < 8; j++)
#pragma unroll
            for (int q = 0; q < 4; q++) acc[i][j][q] = 0.f;

    int a_row  = lane & 15;
    int a_koff = (lane >> 4) * 8;
    int b_row  = (lane & 7) + ((lane >> 4) << 3);
    int b_koff = ((lane >> 3) & 1) * 8;
    uint32_t xbase = sx + (uint32_t)(wm * 32) * ROWB;
    uint32_t wbase = sw + (uint32_t)(wn * 64) * ROWB;

#pragma unroll 4
    for (int kk = 0; kk < 256; kk += 16) {
        uint32_t a[2][4];
#pragma unroll
        for (int mi = 0; mi < 2; mi++)
            ldm4(a[mi], xbase + (uint32_t)(mi * 16 + a_row) * ROWB + (kk + a_koff) * 2);
        uint32_t bfr[4][4];
#pragma unroll
        for (int ni = 0; ni < 4; ni++)
            ldm4(bfr[ni], wbase + (uint32_t)(ni * 16 + b_row) * ROWB + (kk + b_koff) * 2);
#pragma unroll
        for (int mi = 0; mi < 2; mi++)
#pragma unroll
            for (int nj = 0; nj < 8; nj++)
                mma16816(acc[mi][nj], a[mi], bfr[nj >> 1][(nj & 1) * 2],
                         bfr[nj >> 1][(nj & 1) * 2 + 1]);
    }

    int tq = lane >> 2, tr = lane & 3;
    __nv_bfloat16* Yb = Yout + ((size_t)bz * KP + (size_t)bx * 128) * CH + (size_t)by * 128;
#pragma unroll
    for (int mi = 0; mi < 2; mi++) {
#pragma unroll
        for (int nj = 0; nj < 8; nj++) {
            int n = wn * 64 + nj * 8 + tr * 2;
            float b0v = sbias[n], b1v = sbias[n + 1];
            int m0 = wm * 32 + mi * 16 + tq;
#pragma unroll
            for (int h = 0; h < 2; h++) {
                float v0 = acc[mi][nj][h * 2 + 0] + b0v;
                float v1 = acc[mi][nj][h * 2 + 1] + b1v;
                v0 = v0 > 0.f ? v0 : 0.2f * v0;
                v1 = v1 > 0.f ? v1 : 0.2f * v1;
                __nv_bfloat162 pk;
                pk.x = __float2bfloat16_rn(v0);
                pk.y = __float2bfloat16_rn(v1);
                *(__nv_bfloat162*)(Yb + (size_t)(m0 + h * 8) * CH + n) = pk;
            }
        }
    }
}

// ---------------- final head: warp per token ----------------
__global__ void k_final(const float* __restrict__ Wf, const float* __restrict__ bf,
                        float* __restrict__ out) {
    int w = (blockIdx.x * blockDim.x + threadIdx.x) >> 5;
    int lane = threadIdx.x & 31;
    if (w >= BATCH * KTOP) return;
    int b = w / KTOP, t = w - b * KTOP;
    const uint4* x = (const uint4*)(g_xb0 + ((size_t)b * KP + t) * CH);
    uint4 raw = x[lane];
    __nv_bfloat16 h[8];
    *(uint4*)h = raw;
    float l0 = 0.f, l1 = 0.f, l2 = 0.f;
    int c0 = lane * 8;
#pragma unroll
    for (int q = 0; q < 8; q++) {
        float xv = __bfloat162float(h[q]);
        l0 += Wf[c0 + q] * xv;
        l1 += Wf[CH + c0 + q] * xv;
        l2 += Wf[2 * CH + c0 + q] * xv;
    }
#pragma unroll
    for (int o = 16; o; o >>= 1) {
        l0 += __shfl_xor_sync(0xFFFFFFFFu, l0, o);
        l1 += __shfl_xor_sync(0xFFFFFFFFu, l1, o);
        l2 += __shfl_xor_sync(0xFFFFFFFFu, l2, o);
    }
    if (lane == 0) {
        l0 += bf[0]; l1 += bf[1]; l2 += bf[2];
        float m = fmaxf(l0, fmaxf(l1, l2));
        float e0 = expf(l0 - m), e1 = expf(l1 - m), e2 = expf(l2 - m);
        float inv = 1.f / (e0 + e1 + e2);
        unsigned int fl = g_flags[b * KTOP + t];
        float loc = 0.f;
        if (!(fl & 1u)) loc += e0 * inv;
        if (!(fl & 2u)) loc += e1 * inv;
        if (!(fl & 4u)) loc += e2 * inv;
        out[b * KTOP + t] = loc;
    }
}

// ---------------- launch ----------------
extern "C" void kernel_launch(void* const* d_in, const int* in_sizes, int n_in,
                              void* d_out, int out_size) {
    const float* box   = (const float*)d_in[0];
    const float* score = (const float*)d_in[1];
    const float* feat  = (const float*)d_in[2];
    const float* W     = (const float*)d_in[3];
    const float* bvec  = (const float*)d_in[4];
    const float* Wf    = (const float*)d_in[5];
    const float* bf    = (const float*)d_in[6];
    float* out = (float*)d_out;
    int write_keep = (out_size >= 2 * BATCH * KTOP) ? 1 : 0;

    static int init_done = 0;
    static __nv_bfloat16 *x0p = nullptr, *x1p = nullptr;
    if (!init_done) {
        cudaFuncSetAttribute(k_mma, cudaFuncAttributeMaxDynamicSharedMemorySize, SMEM_GEMM);
        cudaGetSymbolAddress((void**)&x0p, g_xb0);
        cudaGetSymbolAddress((void**)&x1p, g_xb1);
        init_done = 1;
    }

    k_prep<<<(NLAYERS * CH * CH + 255) / 256, 256>>>(W);
    s1_hist<<<BATCH, 1024>>>(score);
    s2_scatter<<<(BATCH * NBOX + 255) / 256, 256>>>(score);
    s3_rank<<<dim3(CANDMAX / 256, BATCH), 256>>>(box, out, write_keep);
    k_gather<<<BATCH * KP / 8, 256>>>(feat);
    k_iou<<<dim3(40, 40, BATCH), 128>>>();
    for (int l = 0; l < NLAYERS; l++) {
        const __nv_bfloat16* Xi = (l & 1) ? x1p : x0p;
        __nv_bfloat16*       Yo = (l & 1) ? x0p : x1p;
        k_mma<<<dim3(KP / 128, 2, BATCH), 256, SMEM_GEMM>>>(Xi, Yo, l, bvec);
    }
    k_final<<<(BATCH * KTOP + 7) / 8, 256>>>(Wf, bf, out);
}

// round 10
// speedup vs baseline: 1.5766x; 1.0923x over previous
#include <cuda_runtime.h>
#include <cuda_bf16.h>
#include <cstdint>

#define BATCH 2
#define NBOX  20000
#define CH    256
#define KTOP  5000
#define KP    5120
#define NLAYERS 6
#define CANDMAX 8192
#define NBUCKET 8192

// ---------------- scratch (no allocations allowed) ----------------
__device__ unsigned long long g_cand[BATCH * CANDMAX];
__device__ int            g_thrb[BATCH];
__device__ int            g_bstart[BATCH * NBUCKET];
__device__ int            g_boff[BATCH * NBUCKET];
__device__ int            g_keep[BATCH * KTOP];
__device__ float4         g_boxk[BATCH * KTOP];
__device__ float          g_areak[BATCH * KTOP];
__device__ unsigned int   g_flags[BATCH * KTOP];
__device__ __nv_bfloat16  g_xb0[BATCH * KP * CH];
__device__ __nv_bfloat16  g_xb1[BATCH * KP * CH];
__device__ __nv_bfloat16  g_Wbf[NLAYERS * CH * CH];

__device__ __forceinline__ uint32_t smem_u32(const void* p) {
    uint32_t a;
    asm("{ .reg .u64 t; cvta.to.shared.u64 t, %1; cvt.u32.u64 %0, t; }" : "=r"(a) : "l"(p));
    return a;
}

// ---------------- 0) convert W to bf16 ----------------
__global__ void k_prep(const float* __restrict__ W) {
    int i = blockIdx.x * blockDim.x + threadIdx.x;
    if (i < NLAYERS * CH * CH) g_Wbf[i] = __float2bfloat16_rn(W[i]);
}

// ---------------- 1) histogram -> per-bucket descending start offsets + threshold ----------------
// scores positive floats -> bucket = bits>>19 monotone in score (higher bucket = higher score).
__global__ void s1_hist(const float* __restrict__ score) {
    __shared__ uint32_t hist[NBUCKET];
    __shared__ uint32_t part[1024];
    int b = blockIdx.x, tid = threadIdx.x;
#pragma unroll
    for (int q = 0; q < 8; q++) hist[tid + q * 1024] = 0;
    __syncthreads();
    for (int n = tid; n < NBOX; n += 1024) {
        unsigned bits = __float_as_uint(score[b * NBOX + n]);
        atomicAdd(&hist[bits >> 19], 1u);
    }
    __syncthreads();
    uint32_t cs = 0;
#pragma unroll
    for (int q = 7; q >= 0; q--) cs += hist[tid * 8 + q];
    part[tid] = cs;
    __syncthreads();
    for (int off = 1; off < 1024; off <<= 1) {
        uint32_t v = part[tid] + ((tid + off < 1024) ? part[tid + off] : 0u);
        __syncthreads();
        part[tid] = v;
        __syncthreads();
    }
    uint32_t s = (tid < 1023) ? part[tid + 1] : 0u;   // elems in buckets above this chunk
#pragma unroll
    for (int q = 7; q >= 0; q--) {
        int v = tid * 8 + q;
        g_bstart[b * NBUCKET + v] = (int)s;
        g_boff[b * NBUCKET + v]   = (int)s;
        uint32_t ns = s + hist[v];
        if (s < (uint32_t)KTOP && ns >= (uint32_t)KTOP) g_thrb[b] = v;
        s = ns;
    }
}

// ---------------- 2) counting-sort scatter into bucket regions ----------------
__global__ void s2_scatter(const float* __restrict__ score) {
    int i = blockIdx.x * blockDim.x + threadIdx.x;
    if (i >= BATCH * NBOX) return;
    int b = i / NBOX, n = i - b * NBOX;
    unsigned bits = __float_as_uint(score[b * NBOX + n]);
    int v = (int)(bits >> 19);
    if (v >= g_thrb[b]) {
        int pos = atomicAdd(&g_boff[b * NBUCKET + v], 1);
        if (pos < CANDMAX)
            g_cand[b * CANDMAX + pos] =
                ((unsigned long long)bits << 32) | (0xFFFFFFFFu - (unsigned)n);
    }
}

// ---------------- 3) exact rank within bucket (warp per candidate) + scatter ----------------
__global__ void s3_rank(const float* __restrict__ box, float* __restrict__ out,
                        int write_keep) {
    int b = blockIdx.y;
    int w = (blockIdx.x * blockDim.x + threadIdx.x) >> 5;   // candidate index
    int lane = threadIdx.x & 31;
    int thrb = g_thrb[b];
    int tot = min(g_boff[b * NBUCKET + thrb], CANDMAX);
    if (w >= tot) return;
    unsigned long long key = g_cand[b * CANDMAX + w];
    int v = (int)(key >> 51);                               // bucket
    int s = g_bstart[b * NBUCKET + v];
    int e = min(g_boff[b * NBUCKET + v], CANDMAX);
    const unsigned long long* reg = g_cand + b * CANDMAX;
    int r = 0;
    for (int q = s + lane; q < e; q += 32) r += (reg[q] > key) ? 1 : 0;
#pragma unroll
    for (int o = 16; o; o >>= 1) r += __shfl_xor_sync(0xFFFFFFFFu, r, o);
    if (lane == 0) {
        r += s;
        if (r < KTOP) {
            int idx = (int)(0xFFFFFFFFu - (unsigned)(key & 0xFFFFFFFFull));
            g_keep[b * KTOP + r] = idx;
            g_flags[b * KTOP + r] = 0u;
            const float* bb = box + b * 4 * NBOX;
            float x1 = bb[idx], y1 = bb[NBOX + idx];
            float x2 = bb[2 * NBOX + idx], y2 = bb[3 * NBOX + idx];
            g_boxk[b * KTOP + r] = make_float4(x1, y1, x2, y2);
            g_areak[b * KTOP + r] = (x2 - x1) * (y2 - y1);
            if (write_keep) out[BATCH * KTOP + b * KTOP + r] = (float)idx;
        }
    }
}

// ---------------- gather: token-major bf16, one warp per token ----------------
__global__ void k_gather(const float* __restrict__ feat) {
    int w = (blockIdx.x * blockDim.x + threadIdx.x) >> 5;
    int lane = threadIdx.x & 31;
    if (w >= BATCH * KP) return;
    int b = w / KP, t = w - b * KP;
    uint4* dst = (uint4*)(g_xb0 + (size_t)w * CH);
    if (t >= KTOP) { dst[lane] = make_uint4(0, 0, 0, 0); return; }
    int idx = g_keep[b * KTOP + t];
    const float* f = feat + (size_t)b * CH * NBOX + idx;
    __nv_bfloat16 h[8];
#pragma unroll
    for (int q = 0; q < 8; q++)
        h[q] = __float2bfloat16_rn(f[(size_t)(lane * 8 + q) * NBOX]);
    dst[lane] = *(uint4*)h;
}

// ---------------- IoU local-max flags (division-free) ----------------
__global__ void k_iou() {
    int ti = blockIdx.x, tj = blockIdx.y, b = blockIdx.z;
    if (ti > tj) return;
    __shared__ float4 sbx[128];
    __shared__ float  sar[128];
    int tid = threadIdx.x;
    int gi0 = ti * 128;
    int gl = gi0 + tid;
    if (gl < KTOP) { sbx[tid] = g_boxk[b * KTOP + gl]; sar[tid] = g_areak[b * KTOP + gl]; }
    __syncthreads();
    int j = tj * 128 + tid;
    if (j >= KTOP) return;
    float4 bj = g_boxk[b * KTOP + j];
    float  aj = g_areak[b * KTOP + j];
    int imax = min(KTOP, min(j, gi0 + 128)) - gi0;
    unsigned int fl = 0u;
    for (int i = 0; i < imax; i++) {
        float4 bi = sbx[i];
        float w = fminf(bi.z, bj.z) - fmaxf(bi.x, bj.x);
        float h = fminf(bi.w, bj.w) - fmaxf(bi.y, bj.y);
        w = fmaxf(w, 0.f); h = fmaxf(h, 0.f);
        float inter = w * h;
        float uni = sar[i] + aj - inter;
        if (inter >= 0.4f * uni) fl |= 1u;
        if (inter >= 0.6f * uni) fl |= 2u;
        if (inter >= 0.8f * uni) fl |= 4u;
        if (fl == 7u) break;
    }
    if (fl) atomicOr(&g_flags[b * KTOP + j], fl);
}

// ---------------- bf16 mma.sync layer: 128 tokens x 128 outch x K=256 ----------------
#define ROWB   528
#define TILEB  (128 * ROWB)
#define SMEM_GEMM (2 * TILEB + 512)

__device__ __forceinline__ void ldm4(uint32_t* r, uint32_t addr) {
    asm volatile("ldmatrix.sync.aligned.m8n8.x4.shared.b16 {%0,%1,%2,%3}, [%4];"
                 : "=r"(r[0]), "=r"(r[1]), "=r"(r[2]), "=r"(r[3]) : "r"(addr));
}
__device__ __forceinline__ void mma16816(float* c, const uint32_t* a,
                                         uint32_t b0, uint32_t b1) {
    asm volatile(
        "mma.sync.aligned.m16n8k16.row.col.f32.bf16.bf16.f32 "
        "{%0,%1,%2,%3}, {%4,%5,%6,%7}, {%8,%9}, {%0,%1,%2,%3};"
        : "+f"(c[0]), "+f"(c[1]), "+f"(c[2]), "+f"(c[3])
        : "r"(a[0]), "r"(a[1]), "r"(a[2]), "r"(a[3]), "r"(b0), "r"(b1));
}

__global__ void __launch_bounds__(256, 1)
k_mma(const __nv_bfloat16* __restrict__ Xin, __nv_bfloat16* __restrict__ Yout,
      int layer, const float* __restrict__ bvec) {
    extern __shared__ char smem[];
    float* sbias = (float*)(smem + 2 * TILEB);
    uint32_t sx = smem_u32(smem);
    uint32_t sw = sx + TILEB;
    int tid = threadIdx.x, wid = tid >> 5, lane = tid & 31;
    int bx = blockIdx.x, by = blockIdx.y, bz = blockIdx.z;

    const uint4* gX = (const uint4*)(Xin + ((size_t)bz * KP + (size_t)bx * 128) * CH);
    const uint4* gW = (const uint4*)(g_Wbf + (size_t)layer * CH * CH + (size_t)by * 128 * CH);
#pragma unroll
    for (int it = 0; it < 16; it++) {
        int c = tid + it * 256;
        int row = c >> 5, ch = (c & 31) * 8;
        *(uint4*)(smem + row * ROWB + ch * 2)         = gX[c];
        *(uint4*)(smem + TILEB + row * ROWB + ch * 2) = gW[c];
    }
    if (tid < 128) sbias[tid] = bvec[layer * CH + by * 128 + tid];
    __syncthreads();

    int wm = wid & 3, wn = wid >> 2;
    float acc[2][8][4];
#pragma unroll
    for (int i = 0; i < 2; i++)
#pragma unroll
        for (int j = 0; j < 8; j++)
#pragma unroll
            for (int q = 0; q < 4; q++) acc[i][j][q] = 0.f;

    int a_row  = lane & 15;
    int a_koff = (lane >> 4) * 8;
    int b_row  = (lane & 7) + ((lane >> 4) << 3);
    int b_koff = ((lane >> 3) & 1) * 8;
    uint32_t xbase = sx + (uint32_t)(wm * 32) * ROWB;
    uint32_t wbase = sw + (uint32_t)(wn * 64) * ROWB;

#pragma unroll 4
    for (int kk = 0; kk < 256; kk += 16) {
        uint32_t a[2][4];
#pragma unroll
        for (int mi = 0; mi < 2; mi++)
            ldm4(a[mi], xbase + (uint32_t)(mi * 16 + a_row) * ROWB + (kk + a_koff) * 2);
        uint32_t bfr[4][4];
#pragma unroll
        for (int ni = 0; ni < 4; ni++)
            ldm4(bfr[ni], wbase + (uint32_t)(ni * 16 + b_row) * ROWB + (kk + b_koff) * 2);
#pragma unroll
        for (int mi = 0; mi < 2; mi++)
#pragma unroll
            for (int nj = 0; nj < 8; nj++)
                mma16816(acc[mi][nj], a[mi], bfr[nj >> 1][(nj & 1) * 2],
                         bfr[nj >> 1][(nj & 1) * 2 + 1]);
    }

    int tq = lane >> 2, tr = lane & 3;
    __nv_bfloat16* Yb = Yout + ((size_t)bz * KP + (size_t)bx * 128) * CH + (size_t)by * 128;
#pragma unroll
    for (int mi = 0; mi < 2; mi++) {
#pragma unroll
        for (int nj = 0; nj < 8; nj++) {
            int n = wn * 64 + nj * 8 + tr * 2;
            float b0v = sbias[n], b1v = sbias[n + 1];
            int m0 = wm * 32 + mi * 16 + tq;
#pragma unroll
            for (int h = 0; h < 2; h++) {
                float v0 = acc[mi][nj][h * 2 + 0] + b0v;
                float v1 = acc[mi][nj][h * 2 + 1] + b1v;
                v0 = v0 > 0.f ? v0 : 0.2f * v0;
                v1 = v1 > 0.f ? v1 : 0.2f * v1;
                __nv_bfloat162 pk;
                pk.x = __float2bfloat16_rn(v0);
                pk.y = __float2bfloat16_rn(v1);
                *(__nv_bfloat162*)(Yb + (size_t)(m0 + h * 8) * CH + n) = pk;
            }
        }
    }
}

// ---------------- final head: warp per token ----------------
__global__ void k_final(const float* __restrict__ Wf, const float* __restrict__ bf,
                        float* __restrict__ out) {
    int w = (blockIdx.x * blockDim.x + threadIdx.x) >> 5;
    int lane = threadIdx.x & 31;
    if (w >= BATCH * KTOP) return;
    int b = w / KTOP, t = w - b * KTOP;
    const uint4* x = (const uint4*)(g_xb0 + ((size_t)b * KP + t) * CH);
    uint4 raw = x[lane];
    __nv_bfloat16 h[8];
    *(uint4*)h = raw;
    float l0 = 0.f, l1 = 0.f, l2 = 0.f;
    int c0 = lane * 8;
#pragma unroll
    for (int q = 0; q < 8; q++) {
        float xv = __bfloat162float(h[q]);
        l0 += Wf[c0 + q] * xv;
        l1 += Wf[CH + c0 + q] * xv;
        l2 += Wf[2 * CH + c0 + q] * xv;
    }
#pragma unroll
    for (int o = 16; o; o >>= 1) {
        l0 += __shfl_xor_sync(0xFFFFFFFFu, l0, o);
        l1 += __shfl_xor_sync(0xFFFFFFFFu, l1, o);
        l2 += __shfl_xor_sync(0xFFFFFFFFu, l2, o);
    }
    if (lane == 0) {
        l0 += bf[0]; l1 += bf[1]; l2 += bf[2];
        float m = fmaxf(l0, fmaxf(l1, l2));
        float e0 = expf(l0 - m), e1 = expf(l1 - m), e2 = expf(l2 - m);
        float inv = 1.f / (e0 + e1 + e2);
        unsigned int fl = g_flags[b * KTOP + t];
        float loc = 0.f;
        if (!(fl & 1u)) loc += e0 * inv;
        if (!(fl & 2u)) loc += e1 * inv;
        if (!(fl & 4u)) loc += e2 * inv;
        out[b * KTOP + t] = loc;
    }
}

// ---------------- launch ----------------
extern "C" void kernel_launch(void* const* d_in, const int* in_sizes, int n_in,
                              void* d_out, int out_size) {
    const float* box   = (const float*)d_in[0];
    const float* score = (const float*)d_in[1];
    const float* feat  = (const float*)d_in[2];
    const float* W     = (const float*)d_in[3];
    const float* bvec  = (const float*)d_in[4];
    const float* Wf    = (const float*)d_in[5];
    const float* bf    = (const float*)d_in[6];
    float* out = (float*)d_out;
    int write_keep = (out_size >= 2 * BATCH * KTOP) ? 1 : 0;

    static int init_done = 0;
    static __nv_bfloat16 *x0p = nullptr, *x1p = nullptr;
    if (!init_done) {
        cudaFuncSetAttribute(k_mma, cudaFuncAttributeMaxDynamicSharedMemorySize, SMEM_GEMM);
        cudaGetSymbolAddress((void**)&x0p, g_xb0);
        cudaGetSymbolAddress((void**)&x1p, g_xb1);
        init_done = 1;
    }

    k_prep<<<(NLAYERS * CH * CH + 255) / 256, 256>>>(W);
    s1_hist<<<BATCH, 1024>>>(score);
    s2_scatter<<<(BATCH * NBOX + 255) / 256, 256>>>(score);
    s3_rank<<<dim3(CANDMAX * 32 / 256, BATCH), 256>>>(box, out, write_keep);
    k_gather<<<BATCH * KP / 8, 256>>>(feat);
    k_iou<<<dim3(40, 40, BATCH), 128>>>();
    for (int l = 0; l < NLAYERS; l++) {
        const __nv_bfloat16* Xi = (l & 1) ? x1p : x0p;
        __nv_bfloat16*       Yo = (l & 1) ? x0p : x1p;
        k_mma<<<dim3(KP / 128, 2, BATCH), 256, SMEM_GEMM>>>(Xi, Yo, l, bvec);
    }
    k_final<<<(BATCH * KTOP + 7) / 8, 256>>>(Wf, bf, out);
}